// round 1
// baseline (speedup 1.0000x reference)
#include <cuda_runtime.h>
#include <cstdint>

#define BB 8
#define NN 128
#define KK 16
#define NB (BB*NN)

__device__ __constant__ float c_ALPHA = 0.01f;
__device__ __constant__ float c_LAM   = 1.0f;
__device__ __constant__ float c_KAPPA = 1.0f;
#define EPSV 1e-6f

// scratch (device globals: no allocation allowed)
__device__ float g_E[NB * KK * KK];   // E[bn][k][l] = expm(phi.G)[k][l]
__device__ float g_M[NB * KK * KK];   // M[bn] = F diag(1/(sq+eps)) F^T  (symmetric)
__device__ float g_w[NB * KK];        // w[bn] = F mu_q  (gauge-frame mean)

// ---------------------------------------------------------------------------
// Kernel 1: per (b,n) compute E = expm(A), w, M, and grad_sigma (self term).
// One block of 256 threads per (b,n). thread t -> element (i=t/16, j=t%16).
// ---------------------------------------------------------------------------
__global__ void __launch_bounds__(256) prep_kernel(
    const float* __restrict__ mu_q,
    const float* __restrict__ sigma_q,
    const float* __restrict__ sigma_p,
    const float* __restrict__ phi,
    const float* __restrict__ gen,      // (3,16,16)
    float* __restrict__ out_sigma)      // grad_sigma part of d_out
{
    const int bn = blockIdx.x;
    const int t = threadIdx.x;
    const int i = t >> 4;
    const int j = t & 15;

    __shared__ float sT[256];    // scaled A
    __shared__ float sR[256];    // running matrix
    __shared__ float sE[256];
    __shared__ float sred[16];
    __shared__ int   s_sc;
    __shared__ float smu[16], sr[16];

    const float p0 = phi[bn*3 + 0];
    const float p1 = phi[bn*3 + 1];
    const float p2 = phi[bn*3 + 2];
    float a = p0*gen[t] + p1*gen[256 + t] + p2*gen[512 + t];
    sT[t] = a;            // temporarily holds A
    __syncthreads();

    // inf-norm (max abs row sum)
    if (t < 16) {
        float s = 0.f;
        #pragma unroll
        for (int l = 0; l < 16; l++) s += fabsf(sT[t*16 + l]);
        sred[t] = s;
    }
    __syncthreads();
    if (t == 0) {
        float m = 0.f;
        #pragma unroll
        for (int l = 0; l < 16; l++) m = fmaxf(m, sred[l]);
        int sc = 0;
        while (m > 0.25f && sc < 30) { m *= 0.5f; sc++; }
        s_sc = sc;
    }
    __syncthreads();
    const int sc = s_sc;
    const float scale = ldexpf(1.0f, -sc);
    const float Tt = sT[t] * scale;
    __syncthreads();
    sT[t] = Tt;                                   // T = A / 2^sc, ||T||_inf <= 0.25
    sR[t] = (i == j) ? 1.0f : 0.0f;               // R = I
    __syncthreads();

    // Taylor-Horner degree 12: R = I + (T*R)/m, m = 12..1
    for (int m = 12; m >= 1; m--) {
        float acc = 0.f;
        #pragma unroll
        for (int l = 0; l < 16; l++) acc = fmaf(sT[i*16 + l], sR[l*16 + j], acc);
        __syncthreads();
        sR[t] = ((i == j) ? 1.0f : 0.0f) + acc / (float)m;
        __syncthreads();
    }
    // squaring: R <- R*R, sc times
    for (int q = 0; q < sc; q++) {
        float acc = 0.f;
        #pragma unroll
        for (int l = 0; l < 16; l++) acc = fmaf(sR[i*16 + l], sR[l*16 + j], acc);
        __syncthreads();
        sR[t] = acc;
        __syncthreads();
    }
    sE[t] = sR[t];   // E = expm(A); F = expm(-A) = E^T (antisymmetric A)
    __syncthreads();

    if (t < 16) {
        smu[t] = mu_q[bn*KK + t];
        const float sq = fmaxf(sigma_q[bn*KK + t], EPSV);
        sr[t] = 1.0f / (sq + EPSV);
        const float sp = fmaxf(sigma_p[bn*KK + t], EPSV);
        out_sigma[bn*KK + t] = c_ALPHA * 0.5f * (1.0f/sp - 1.0f/sq);
    }
    __syncthreads();

    if (t < 16) {
        // w[k] = sum_l F[k][l] mu[l] = sum_l E[l][k] mu[l]
        float acc = 0.f;
        #pragma unroll
        for (int l = 0; l < 16; l++) acc = fmaf(sE[l*16 + t], smu[l], acc);
        g_w[bn*KK + t] = acc;
    }
    // M[i][j] = sum_l E[l][i] * r[l] * E[l][j]   (symmetric)
    {
        float acc = 0.f;
        #pragma unroll
        for (int l = 0; l < 16; l++) acc = fmaf(sE[l*16 + i] * sr[l], sE[l*16 + j], acc);
        g_M[bn*256 + t] = acc;
    }
    g_E[bn*256 + t] = sE[t];
}

// ---------------------------------------------------------------------------
// Kernel 2: per row (b,i) accumulate over j:
//   d    = w_i - w_j                    (gauge frame, lane = component k)
//   y    = M_j d
//   kl   = 0.5 d.y
//   s1 += beta_ij y ; s2 += kl*beta_ij y ; s3 += kl*beta_ij
// final: grad_mu = self + E_i (LAM*s1 + LAM/KAPPA*(s2 - s3*s1))
// 128 threads/block = 8 groups of 16 lanes; all 8 rows share the same b,
// so M_j chunks are staged into smem once per block.
// ---------------------------------------------------------------------------
__global__ void __launch_bounds__(128) pair_kernel(
    const float* __restrict__ mu_q,
    const float* __restrict__ mu_p,
    const float* __restrict__ sigma_p,
    const float* __restrict__ beta,
    float* __restrict__ out_mu)
{
    __shared__ float sM[8 * 256];   // 8 M matrices (column-major == row-major: symmetric)
    __shared__ float swc[8 * 16];   // 8 w vectors
    __shared__ float sd[8 * 16];    // per-group d / v vector

    const int tid  = threadIdx.x;
    const int g    = tid >> 4;
    const int lane = tid & 15;
    const int bn   = blockIdx.x * 8 + g;     // 8 consecutive rows, same b (128 % 8 == 0)
    const int b    = bn >> 7;
    const int irow = bn & 127;

    const float wi = g_w[bn*KK + lane];
    const float* __restrict__ betarow = beta + (size_t)(b*NN + irow) * NN;

    float s1 = 0.f, s2 = 0.f, s3 = 0.f;

    for (int j0 = 0; j0 < NN; j0 += 8) {
        __syncthreads();
        // cooperative stage: 8 matrices = 2048 floats = 512 float4, 128 threads
        {
            const float4* src = reinterpret_cast<const float4*>(g_M + (size_t)(b*NN + j0) * 256);
            float4* dst = reinterpret_cast<float4*>(sM);
            #pragma unroll
            for (int q = 0; q < 4; q++) dst[tid + q*128] = src[tid + q*128];
            swc[tid] = g_w[(size_t)(b*NN + j0) * KK + tid];
        }
        __syncthreads();

        #pragma unroll
        for (int jj = 0; jj < 8; jj++) {
            const float d = wi - swc[jj*16 + lane];
            sd[g*16 + lane] = d;
            __syncwarp();

            // y = M_j d : column-major walk -> lanes read consecutive addrs (conflict-free)
            const float* __restrict__ Mc = sM + jj*256;
            float y0 = 0.f, y1 = 0.f;
            #pragma unroll
            for (int l = 0; l < 16; l += 2) {
                y0 = fmaf(Mc[ l     *16 + lane], sd[g*16 + l    ], y0);
                y1 = fmaf(Mc[(l + 1)*16 + lane], sd[g*16 + l + 1], y1);
            }
            const float y = y0 + y1;

            // kl = 0.5 * sum_k d_k y_k (reduce across 16-lane group; xor<=8 stays in half)
            float tdy = d * y;
            tdy += __shfl_xor_sync(0xffffffffu, tdy, 1);
            tdy += __shfl_xor_sync(0xffffffffu, tdy, 2);
            tdy += __shfl_xor_sync(0xffffffffu, tdy, 4);
            tdy += __shfl_xor_sync(0xffffffffu, tdy, 8);
            const float kl  = 0.5f * tdy;
            const float bij = __ldg(betarow + j0 + jj);
            const float klb = kl * bij;

            s1 = fmaf(bij, y, s1);
            s2 = fmaf(klb, y, s2);
            s3 += klb;
        }
    }

    // v (gauge frame) = LAM*s1 + (LAM/KAPPA)*(s2 - s3*s1)
    const float v = c_LAM * s1 + (c_LAM / c_KAPPA) * (s2 - s3 * s1);
    __syncwarp();
    sd[g*16 + lane] = v;
    __syncwarp();

    // rotate to global frame: out_k = sum_l E_i[k][l] v[l]
    const float* __restrict__ Erow = g_E + (size_t)bn*256 + lane*16;
    float o = 0.f;
    #pragma unroll
    for (int l = 0; l < 16; l++) o = fmaf(Erow[l], sd[g*16 + l], o);

    const float sp   = fmaxf(sigma_p[bn*KK + lane], EPSV);
    const float self = c_ALPHA * (mu_q[bn*KK + lane] - mu_p[bn*KK + lane]) / sp;

    out_mu[bn*KK + lane] = self + o;
}

// ---------------------------------------------------------------------------
extern "C" void kernel_launch(void* const* d_in, const int* in_sizes, int n_in,
                              void* d_out, int out_size)
{
    const float* mu_q    = (const float*)d_in[0];
    const float* sigma_q = (const float*)d_in[1];
    const float* mu_p    = (const float*)d_in[2];
    const float* sigma_p = (const float*)d_in[3];
    const float* beta    = (const float*)d_in[4];
    const float* phi     = (const float*)d_in[5];
    const float* gen     = (const float*)d_in[6];

    float* out   = (float*)d_out;
    float* out_mu    = out;                 // (B,N,K) = 16384 floats
    float* out_sigma = out + NB*KK;         // (B,N,K) = 16384 floats

    prep_kernel<<<NB, 256>>>(mu_q, sigma_q, sigma_p, phi, gen, out_sigma);
    pair_kernel<<<NB/8, 128>>>(mu_q, mu_p, sigma_p, beta, out_mu);
}

// round 2
// speedup vs baseline: 1.7770x; 1.7770x over previous
#include <cuda_runtime.h>
#include <cstdint>

#define BB 8
#define NN 128
#define KK 16
#define NB (BB*NN)
#define JSPLIT 8
#define JCHUNK (NN/JSPLIT)   // 16
#define RPB 16               // rows per block in pairA

#define ALPHA_C 0.01f
#define LAM_C   1.0f
#define KAPPA_C 1.0f
#define EPSV    1e-6f

// scratch (device globals: no allocation allowed)
__device__ float g_E[NB * 256];          // E[bn] = expm(phi.G), row-major
__device__ float g_M[NB * 256];          // M[bn] = F diag(1/(sq+eps)) F^T (symmetric)
__device__ float g_w[NB * KK];           // w = F mu_q
__device__ float g_u[NB * KK];           // u = M w = F (r .* mu_q)
__device__ float g_s1[JSPLIT * NB * KK]; // partial sums, layout [split][bn][k]
__device__ float g_s2[JSPLIT * NB * KK];
__device__ float g_s3[JSPLIT * NB];

// ---------------------------------------------------------------------------
// Kernel 1: per (b,n): E = expm(A) (scaling+squaring, Taylor-12, ping-pong
// buffers: ONE barrier per iteration), then w, u, M, grad_sigma self term.
// thread t -> element (i=t>>4, j=t&15).
// ---------------------------------------------------------------------------
__global__ void __launch_bounds__(256) prep_kernel(
    const float* __restrict__ mu_q,
    const float* __restrict__ sigma_q,
    const float* __restrict__ sigma_p,
    const float* __restrict__ phi,
    const float* __restrict__ gen,
    float* __restrict__ out_sigma)
{
    const int bn = blockIdx.x;
    const int t  = threadIdx.x;
    const int i  = t >> 4;
    const int j  = t & 15;

    __shared__ float sT[256];
    __shared__ float sB[2][256];
    __shared__ float sred[16];
    __shared__ float smu[16], sr[16];

    const float p0 = __ldg(&phi[bn*3 + 0]);
    const float p1 = __ldg(&phi[bn*3 + 1]);
    const float p2 = __ldg(&phi[bn*3 + 2]);
    const float a = p0*gen[t] + p1*gen[256 + t] + p2*gen[512 + t];

    if (t < 16) {
        const float mu = mu_q[bn*KK + t];
        const float sq = fmaxf(sigma_q[bn*KK + t], EPSV);
        const float sp = fmaxf(sigma_p[bn*KK + t], EPSV);
        smu[t] = mu;
        sr[t]  = 1.0f / (sq + EPSV);
        out_sigma[bn*KK + t] = ALPHA_C * 0.5f * (1.0f/sp - 1.0f/sq);
    }

    // row inf-norm via 16-lane shfl reduce (row i is a half-warp segment)
    float rs = fabsf(a);
    rs += __shfl_xor_sync(0xffffffffu, rs, 1);
    rs += __shfl_xor_sync(0xffffffffu, rs, 2);
    rs += __shfl_xor_sync(0xffffffffu, rs, 4);
    rs += __shfl_xor_sync(0xffffffffu, rs, 8);
    if (j == 0) sred[i] = rs;
    __syncthreads();

    float nrm = 0.f;
    #pragma unroll
    for (int l = 0; l < 16; l++) nrm = fmaxf(nrm, sred[l]);
    int sc = 0;
    while (nrm > 1.0f && sc < 24) { nrm *= 0.5f; sc++; }  // uniform across block

    sT[t]    = a * ldexpf(1.0f, -sc);
    sB[0][t] = (i == j) ? 1.0f : 0.0f;
    __syncthreads();

    // Taylor-Horner degree 12, ping-pong: one barrier per iteration
    int cur = 0;
    #pragma unroll
    for (int mm = 12; mm >= 1; mm--) {
        float acc = 0.f;
        #pragma unroll
        for (int l = 0; l < 16; l++)
            acc = fmaf(sT[i*16 + l], sB[cur][l*16 + j], acc);
        sB[cur ^ 1][t] = ((i == j) ? 1.0f : 0.0f) + acc * (1.0f / (float)mm);
        __syncthreads();
        cur ^= 1;
    }
    // squarings
    for (int q = 0; q < sc; q++) {
        float acc = 0.f;
        #pragma unroll
        for (int l = 0; l < 16; l++)
            acc = fmaf(sB[cur][i*16 + l], sB[cur][l*16 + j], acc);
        sB[cur ^ 1][t] = acc;
        __syncthreads();
        cur ^= 1;
    }
    const float* sE = sB[cur];   // E = expm(A);  F = E^T

    g_E[(size_t)bn*256 + t] = sE[t];

    // M[i][j] = sum_l E[l][i] r[l] E[l][j]
    {
        float acc = 0.f;
        #pragma unroll
        for (int l = 0; l < 16; l++)
            acc = fmaf(sE[l*16 + i] * sr[l], sE[l*16 + j], acc);
        g_M[(size_t)bn*256 + t] = acc;
    }
    // w[k] = sum_l E[l][k] mu[l],  u[k] = sum_l E[l][k] r[l] mu[l]  (= M w)
    if (t < 16) {
        float wacc = 0.f, uacc = 0.f;
        #pragma unroll
        for (int l = 0; l < 16; l++) {
            const float e = sE[l*16 + t];
            wacc = fmaf(e, smu[l],          wacc);
            uacc = fmaf(e, sr[l] * smu[l],  uacc);
        }
        g_w[bn*KK + t] = wacc;
        g_u[bn*KK + t] = uacc;
    }
}

// ---------------------------------------------------------------------------
// Kernel 2 (phase A): partial j-sums. Grid (JSPLIT, NB/RPB), 256 threads =
// 16 groups of 16 lanes, each group = one row; all 16 rows share the staged
// M/w/u chunk for this block's 16 j's.
//   z = M_j w_i   (w_i in registers, constant-indexed)
//   y = z - u_j ;  d = w_i - w_j ;  kl = 0.5 d.y
//   s1 += b y ; s2 += kl b y ; s3 += kl b
// ---------------------------------------------------------------------------
__global__ void __launch_bounds__(256) pairA_kernel(
    const float* __restrict__ beta)
{
    __shared__ float sM[JCHUNK * 256];   // 16 KB
    __shared__ float swv[JCHUNK * 16];
    __shared__ float suv[JCHUNK * 16];

    const int tid   = threadIdx.x;
    const int g     = tid >> 4;
    const int lane  = tid & 15;
    const int split = blockIdx.x;
    const int bn    = blockIdx.y * RPB + g;   // 16 rows, same b (16 | 128)
    const int b     = bn >> 7;
    const int irow  = bn & 127;
    const int j0    = split * JCHUNK;

    // stage chunk: 16 matrices (1024 float4) + w + u vectors
    {
        const float4* src = reinterpret_cast<const float4*>(g_M + (size_t)(b*NN + j0) * 256);
        float4* dst = reinterpret_cast<float4*>(sM);
        #pragma unroll
        for (int q = 0; q < 4; q++) dst[q*256 + tid] = src[q*256 + tid];
        swv[tid] = g_w[(size_t)(b*NN + j0) * KK + tid];
        suv[tid] = g_u[(size_t)(b*NN + j0) * KK + tid];
    }

    // w_i into registers (constant-indexed in the unrolled matvec)
    float wir[16];
    {
        const float4* wp = reinterpret_cast<const float4*>(g_w + (size_t)bn * KK);
        #pragma unroll
        for (int q = 0; q < 4; q++) {
            const float4 v4 = wp[q];
            wir[q*4+0] = v4.x; wir[q*4+1] = v4.y; wir[q*4+2] = v4.z; wir[q*4+3] = v4.w;
        }
    }
    const float wi_self = g_w[(size_t)bn*KK + lane];
    const float* __restrict__ betarow = beta + (size_t)(b*NN + irow) * NN + j0;

    __syncthreads();

    float s1 = 0.f, s2 = 0.f, s3 = 0.f;

    #pragma unroll
    for (int jj = 0; jj < JCHUNK; jj++) {
        const float* __restrict__ Mc = sM + jj*256;   // symmetric: col-major == row-major
        float z0 = 0.f, z1 = 0.f;
        #pragma unroll
        for (int l = 0; l < 16; l += 2) {
            z0 = fmaf(Mc[ l     *16 + lane], wir[l    ], z0);
            z1 = fmaf(Mc[(l + 1)*16 + lane], wir[l + 1], z1);
        }
        const float y = (z0 + z1) - suv[jj*16 + lane];
        const float d = wi_self   - swv[jj*16 + lane];

        float tt = d * y;   // reduce within 16-lane group (xor<=8 stays in-group)
        tt += __shfl_xor_sync(0xffffffffu, tt, 1);
        tt += __shfl_xor_sync(0xffffffffu, tt, 2);
        tt += __shfl_xor_sync(0xffffffffu, tt, 4);
        tt += __shfl_xor_sync(0xffffffffu, tt, 8);
        const float kl  = 0.5f * tt;
        const float bij = __ldg(betarow + jj);
        const float klb = kl * bij;

        s1 = fmaf(bij, y, s1);
        s2 = fmaf(klb, y, s2);
        s3 += klb;
    }

    const int idx = split * (NB*KK) + bn*KK + lane;
    g_s1[idx] = s1;
    g_s2[idx] = s2;
    if (lane == 0) g_s3[split * NB + bn] = s3;
}

// ---------------------------------------------------------------------------
// Kernel 3 (finish): combine splits, rotate to global frame by E_i, add self.
// ---------------------------------------------------------------------------
__global__ void __launch_bounds__(256) finish_kernel(
    const float* __restrict__ mu_q,
    const float* __restrict__ mu_p,
    const float* __restrict__ sigma_p,
    float* __restrict__ out_mu)
{
    const int tid  = threadIdx.x;
    const int g    = tid >> 4;
    const int lane = tid & 15;
    const int bn   = blockIdx.x * 16 + g;

    float s1 = 0.f, s2 = 0.f, s3 = 0.f;
    #pragma unroll
    for (int s = 0; s < JSPLIT; s++) {
        s1 += g_s1[s*(NB*KK) + bn*KK + lane];
        s2 += g_s2[s*(NB*KK) + bn*KK + lane];
        s3 += g_s3[s*NB + bn];
    }
    const float v = LAM_C * s1 + (LAM_C / KAPPA_C) * (s2 - s3 * s1);

    // rotate: out_k = sum_l E[k][l] v[l]; lane = k, E row via float4
    float er[16];
    {
        const float4* ep = reinterpret_cast<const float4*>(g_E + (size_t)bn*256 + lane*16);
        #pragma unroll
        for (int q = 0; q < 4; q++) {
            const float4 t4 = ep[q];
            er[q*4+0] = t4.x; er[q*4+1] = t4.y; er[q*4+2] = t4.z; er[q*4+3] = t4.w;
        }
    }
    float o = 0.f;
    #pragma unroll
    for (int l = 0; l < 16; l++)
        o = fmaf(er[l], __shfl_sync(0xffffffffu, v, l, 16), o);

    const float sp   = fmaxf(sigma_p[bn*KK + lane], EPSV);
    const float self = ALPHA_C * (mu_q[bn*KK + lane] - mu_p[bn*KK + lane]) / sp;

    out_mu[bn*KK + lane] = self + o;
}

// ---------------------------------------------------------------------------
extern "C" void kernel_launch(void* const* d_in, const int* in_sizes, int n_in,
                              void* d_out, int out_size)
{
    const float* mu_q    = (const float*)d_in[0];
    const float* sigma_q = (const float*)d_in[1];
    const float* mu_p    = (const float*)d_in[2];
    const float* sigma_p = (const float*)d_in[3];
    const float* beta    = (const float*)d_in[4];
    const float* phi     = (const float*)d_in[5];
    const float* gen     = (const float*)d_in[6];

    float* out       = (float*)d_out;
    float* out_mu    = out;            // (B,N,K)
    float* out_sigma = out + NB*KK;    // (B,N,K)

    prep_kernel<<<NB, 256>>>(mu_q, sigma_q, sigma_p, phi, gen, out_sigma);
    pairA_kernel<<<dim3(JSPLIT, NB/RPB), 256>>>(beta);
    finish_kernel<<<NB/16, 256>>>(mu_q, mu_p, sigma_p, out_mu);
}

// round 4
// speedup vs baseline: 2.1090x; 1.1868x over previous
#include <cuda_runtime.h>
#include <cstdint>

#define BB 8
#define NN 128
#define KK 16
#define NB (BB*NN)
#define JSPLIT 8
#define JCHUNK (NN/JSPLIT)   // 16
#define RPB 16               // rows per block in pairA

#define ALPHA_C 0.01f
#define LAM_C   1.0f
#define KAPPA_C 1.0f
#define EPSV    1e-6f

// scratch (device globals: no allocation allowed)
__device__ float g_E[NB * 256];          // E[bn] = expm(phi.G), row-major
__device__ float g_M[NB * 256];          // M[bn] = F diag(1/(sq+eps)) F^T (symmetric)
__device__ float g_w[NB * KK];           // w = F mu_q
__device__ float g_u[NB * KK];           // u = M w
__device__ float g_s1[JSPLIT * NB * KK];
__device__ float g_s2[JSPLIT * NB * KK];
__device__ float g_s3[JSPLIT * NB];

// ---------------------------------------------------------------------------
// Warp-register 16x16 matmul. Layout: lane = 2*i + jh (i = row, jh = column
// half); each lane holds 8 floats = row i, cols [jh*8, jh*8+8).
// C = T * B. C may alias T and/or B (local accum, write-back at end).
// ---------------------------------------------------------------------------
__device__ __forceinline__ void wmm(const float* T, const float* Bm, float* C, int jh)
{
    float trow[16];
    #pragma unroll
    for (int m = 0; m < 8; m++) {
        const float other = __shfl_xor_sync(0xffffffffu, T[m], 1);
        trow[jh*8 + m]       = T[m];
        trow[(1 - jh)*8 + m] = other;
    }
    float c[8] = {0.f,0.f,0.f,0.f,0.f,0.f,0.f,0.f};
    #pragma unroll
    for (int l = 0; l < 16; l++) {
        const int src = l*2 + jh;
        #pragma unroll
        for (int m = 0; m < 8; m++) {
            const float b = __shfl_sync(0xffffffffu, Bm[m], src);
            c[m] = fmaf(trow[l], b, c[m]);
        }
    }
    #pragma unroll
    for (int m = 0; m < 8; m++) C[m] = c[m];
}

// ---------------------------------------------------------------------------
// Kernel 1: warp-per-matrix expm via even/odd Paterson-Stockmeyer Taylor-13
// + scaling/squaring. Then E, M, w, u, grad_sigma.
// Block = 128 threads = 4 warps = 4 matrices.
// ---------------------------------------------------------------------------
__global__ void __launch_bounds__(128) prep_kernel(
    const float* __restrict__ mu_q,
    const float* __restrict__ sigma_q,
    const float* __restrict__ sigma_p,
    const float* __restrict__ phi,
    const float* __restrict__ gen,
    float* __restrict__ out_sigma)
{
    const int wid  = threadIdx.x >> 5;
    const int lane = threadIdx.x & 31;
    const int i    = lane >> 1;
    const int jh   = lane & 1;
    const int bn   = blockIdx.x * 4 + wid;

    __shared__ float sEall[4][272];   // per-warp E stage (16x16 + pad)
    __shared__ float sAux[4][48];     // per-warp: r[16], mu[16], rmu[16]
    float* sE = sEall[wid];
    float* sr  = sAux[wid];
    float* smu = sAux[wid] + 16;
    float* srm = sAux[wid] + 32;

    // ---- A = phi . G  (each lane: its 8 elements) ----
    const float p0 = __ldg(&phi[bn*3 + 0]);
    const float p1 = __ldg(&phi[bn*3 + 1]);
    const float p2 = __ldg(&phi[bn*3 + 2]);

    float A[8];
    {
        const int base = i*16 + jh*8;
        #pragma unroll
        for (int m = 0; m < 8; m++)
            A[m] = p0*__ldg(&gen[base + m]) + p1*__ldg(&gen[256 + base + m])
                 + p2*__ldg(&gen[512 + base + m]);
    }

    // aux loads (lanes 0..15)
    if (lane < 16) {
        const float mu = mu_q[bn*KK + lane];
        const float sq = fmaxf(sigma_q[bn*KK + lane], EPSV);
        const float sp = fmaxf(sigma_p[bn*KK + lane], EPSV);
        const float r  = 1.0f / (sq + EPSV);
        sr[lane]  = r;
        smu[lane] = mu;
        srm[lane] = r * mu;
        out_sigma[bn*KK + lane] = ALPHA_C * 0.5f * (1.0f/sp - 1.0f/sq);
    }

    // ---- inf-norm and scaling ----
    float s = 0.f;
    #pragma unroll
    for (int m = 0; m < 8; m++) s += fabsf(A[m]);
    s += __shfl_xor_sync(0xffffffffu, s, 1);           // full row sum
    s = fmaxf(s, __shfl_xor_sync(0xffffffffu, s, 2));
    s = fmaxf(s, __shfl_xor_sync(0xffffffffu, s, 4));
    s = fmaxf(s, __shfl_xor_sync(0xffffffffu, s, 8));
    s = fmaxf(s, __shfl_xor_sync(0xffffffffu, s, 16)); // max over rows

    int sc = 0;
    while (s > 2.0f && sc < 24) { s *= 0.5f; sc++; }
    const float scale = ldexpf(1.0f, -sc);
    #pragma unroll
    for (int m = 0; m < 8; m++) A[m] *= scale;

    // diagonal ownership: element (i, i) is in my regs iff (i>>3)==jh, at m=i&7
    const bool hasdiag = ((i >> 3) == jh);
    const int  dm      = i & 7;

    // ---- powers ----
    float X[8], X2[8], X3[8];
    wmm(A,  A,  X,  jh);    // X  = A^2
    wmm(X,  X,  X2, jh);    // X2 = A^4
    wmm(X2, X,  X3, jh);    // X3 = A^6

    // Taylor-13 even/odd coefficients
    const float c1 = 1.f/2.f,  c2 = 1.f/24.f,   c3 = 1.f/720.f;
    const float c4 = 1.f/40320.f, c5 = 1.f/3628800.f, c6 = 1.f/479001600.f;
    const float d1 = 1.f/6.f,  d2 = 1.f/120.f,  d3 = 1.f/5040.f;
    const float d4 = 1.f/362880.f, d5 = 1.f/39916800.f, d6 = 6.0590591e-10f; // 1/13!

    float tmp[8], P[8], Q[8];
    // P = I + c1 X + c2 X2 + c3 X3 + X3*(c4 X + c5 X2 + c6 X3)
    #pragma unroll
    for (int m = 0; m < 8; m++)
        tmp[m] = fmaf(c4, X[m], fmaf(c5, X2[m], c6 * X3[m]));
    wmm(X3, tmp, tmp, jh);
    #pragma unroll
    for (int m = 0; m < 8; m++)
        P[m] = fmaf(c1, X[m], fmaf(c2, X2[m], fmaf(c3, X3[m], tmp[m])));
    if (hasdiag) P[dm] += 1.0f;

    // Q = I + d1 X + d2 X2 + d3 X3 + X3*(d4 X + d5 X2 + d6 X3)
    #pragma unroll
    for (int m = 0; m < 8; m++)
        tmp[m] = fmaf(d4, X[m], fmaf(d5, X2[m], d6 * X3[m]));
    wmm(X3, tmp, tmp, jh);
    #pragma unroll
    for (int m = 0; m < 8; m++)
        Q[m] = fmaf(d1, X[m], fmaf(d2, X2[m], fmaf(d3, X3[m], tmp[m])));
    if (hasdiag) Q[dm] += 1.0f;

    // R = P + A*Q
    float R[8];
    wmm(A, Q, R, jh);
    #pragma unroll
    for (int m = 0; m < 8; m++) R[m] += P[m];

    // squarings
    for (int q = 0; q < sc; q++) wmm(R, R, R, jh);

    // ---- write E, stage to smem for transposed accesses ----
    {
        float4* eg = reinterpret_cast<float4*>(g_E + (size_t)bn*256 + i*16 + jh*8);
        eg[0] = make_float4(R[0], R[1], R[2], R[3]);
        eg[1] = make_float4(R[4], R[5], R[6], R[7]);
        float* es = sE + i*16 + jh*8;
        #pragma unroll
        for (int m = 0; m < 8; m++) es[m] = R[m];
    }
    __syncwarp();

    // ---- M[i][j] = sum_l E[l][i] r[l] E[l][j]  (symmetric) ----
    {
        float acc[8] = {0.f,0.f,0.f,0.f,0.f,0.f,0.f,0.f};
        #pragma unroll
        for (int l = 0; l < 16; l++) {
            const float eli_r = sE[l*16 + i] * sr[l];
            const float4 e0 = *reinterpret_cast<const float4*>(sE + l*16 + jh*8);
            const float4 e1 = *reinterpret_cast<const float4*>(sE + l*16 + jh*8 + 4);
            acc[0] = fmaf(eli_r, e0.x, acc[0]);
            acc[1] = fmaf(eli_r, e0.y, acc[1]);
            acc[2] = fmaf(eli_r, e0.z, acc[2]);
            acc[3] = fmaf(eli_r, e0.w, acc[3]);
            acc[4] = fmaf(eli_r, e1.x, acc[4]);
            acc[5] = fmaf(eli_r, e1.y, acc[5]);
            acc[6] = fmaf(eli_r, e1.z, acc[6]);
            acc[7] = fmaf(eli_r, e1.w, acc[7]);
        }
        float4* mg = reinterpret_cast<float4*>(g_M + (size_t)bn*256 + i*16 + jh*8);
        mg[0] = make_float4(acc[0], acc[1], acc[2], acc[3]);
        mg[1] = make_float4(acc[4], acc[5], acc[6], acc[7]);
    }

    // ---- w[k] = sum_l E[l][k] mu[l];  u[k] = sum_l E[l][k] r[l] mu[l] ----
    if (lane < 16) {
        float wacc = 0.f, uacc = 0.f;
        #pragma unroll
        for (int l = 0; l < 16; l++) {
            const float e = sE[l*16 + lane];
            wacc = fmaf(e, smu[l], wacc);
            uacc = fmaf(e, srm[l], uacc);
        }
        g_w[bn*KK + lane] = wacc;
        g_u[bn*KK + lane] = uacc;
    }
}

// ---------------------------------------------------------------------------
// Kernel 2 (phase A): partial j-sums. Grid (JSPLIT, NB/RPB), 256 threads =
// 16 groups of 16 lanes (one row each); 16 rows share the staged chunk.
// ---------------------------------------------------------------------------
__global__ void __launch_bounds__(256) pairA_kernel(
    const float* __restrict__ beta)
{
    __shared__ float sM[JCHUNK * 256];   // 16 KB
    __shared__ float swv[JCHUNK * 16];
    __shared__ float suv[JCHUNK * 16];

    const int tid   = threadIdx.x;
    const int g     = tid >> 4;
    const int lane  = tid & 15;
    const int split = blockIdx.x;
    const int bn    = blockIdx.y * RPB + g;
    const int b     = bn >> 7;
    const int irow  = bn & 127;
    const int j0    = split * JCHUNK;

    {
        const float4* src = reinterpret_cast<const float4*>(g_M + (size_t)(b*NN + j0) * 256);
        float4* dst = reinterpret_cast<float4*>(sM);
        #pragma unroll
        for (int q = 0; q < 4; q++) dst[q*256 + tid] = src[q*256 + tid];
        swv[tid] = g_w[(size_t)(b*NN + j0) * KK + tid];
        suv[tid] = g_u[(size_t)(b*NN + j0) * KK + tid];
    }

    float wir[16];
    {
        const float4* wp = reinterpret_cast<const float4*>(g_w + (size_t)bn * KK);
        #pragma unroll
        for (int q = 0; q < 4; q++) {
            const float4 v4 = wp[q];
            wir[q*4+0] = v4.x; wir[q*4+1] = v4.y; wir[q*4+2] = v4.z; wir[q*4+3] = v4.w;
        }
    }
    const float wi_self = wir[0] * 0.f + g_w[(size_t)bn*KK + lane]; // lane component
    const float* __restrict__ betarow = beta + (size_t)(b*NN + irow) * NN + j0;

    __syncthreads();

    float s1 = 0.f, s2 = 0.f, s3 = 0.f;

    #pragma unroll
    for (int jj = 0; jj < JCHUNK; jj++) {
        const float* __restrict__ Mc = sM + jj*256;
        float z0 = 0.f, z1 = 0.f;
        #pragma unroll
        for (int l = 0; l < 16; l += 2) {
            z0 = fmaf(Mc[ l     *16 + lane], wir[l    ], z0);
            z1 = fmaf(Mc[(l + 1)*16 + lane], wir[l + 1], z1);
        }
        const float y = (z0 + z1) - suv[jj*16 + lane];
        const float d = wi_self   - swv[jj*16 + lane];

        float tt = d * y;
        tt += __shfl_xor_sync(0xffffffffu, tt, 1);
        tt += __shfl_xor_sync(0xffffffffu, tt, 2);
        tt += __shfl_xor_sync(0xffffffffu, tt, 4);
        tt += __shfl_xor_sync(0xffffffffu, tt, 8);
        const float kl  = 0.5f * tt;
        const float bij = __ldg(betarow + jj);
        const float klb = kl * bij;

        s1 = fmaf(bij, y, s1);
        s2 = fmaf(klb, y, s2);
        s3 += klb;
    }

    const int idx = split * (NB*KK) + bn*KK + lane;
    g_s1[idx] = s1;
    g_s2[idx] = s2;
    if (lane == 0) g_s3[split * NB + bn] = s3;
}

// ---------------------------------------------------------------------------
// Kernel 3: combine splits, rotate by E_i, add self term.
// ---------------------------------------------------------------------------
__global__ void __launch_bounds__(256) finish_kernel(
    const float* __restrict__ mu_q,
    const float* __restrict__ mu_p,
    const float* __restrict__ sigma_p,
    float* __restrict__ out_mu)
{
    const int tid  = threadIdx.x;
    const int g    = tid >> 4;
    const int lane = tid & 15;
    const int bn   = blockIdx.x * 16 + g;

    float s1 = 0.f, s2 = 0.f, s3 = 0.f;
    #pragma unroll
    for (int s = 0; s < JSPLIT; s++) {
        s1 += g_s1[s*(NB*KK) + bn*KK + lane];
        s2 += g_s2[s*(NB*KK) + bn*KK + lane];
        s3 += g_s3[s*NB + bn];
    }
    const float v = LAM_C * s1 + (LAM_C / KAPPA_C) * (s2 - s3 * s1);

    float er[16];
    {
        const float4* ep = reinterpret_cast<const float4*>(g_E + (size_t)bn*256 + lane*16);
        #pragma unroll
        for (int q = 0; q < 4; q++) {
            const float4 t4 = ep[q];
            er[q*4+0] = t4.x; er[q*4+1] = t4.y; er[q*4+2] = t4.z; er[q*4+3] = t4.w;
        }
    }
    float o = 0.f;
    #pragma unroll
    for (int l = 0; l < 16; l++)
        o = fmaf(er[l], __shfl_sync(0xffffffffu, v, l, 16), o);

    const float sp   = fmaxf(sigma_p[bn*KK + lane], EPSV);
    const float self = ALPHA_C * (mu_q[bn*KK + lane] - mu_p[bn*KK + lane]) / sp;

    out_mu[bn*KK + lane] = self + o;
}

// ---------------------------------------------------------------------------
extern "C" void kernel_launch(void* const* d_in, const int* in_sizes, int n_in,
                              void* d_out, int out_size)
{
    const float* mu_q    = (const float*)d_in[0];
    const float* sigma_q = (const float*)d_in[1];
    const float* mu_p    = (const float*)d_in[2];
    const float* sigma_p = (const float*)d_in[3];
    const float* beta    = (const float*)d_in[4];
    const float* phi     = (const float*)d_in[5];
    const float* gen     = (const float*)d_in[6];

    float* out       = (float*)d_out;
    float* out_mu    = out;            // (B,N,K)
    float* out_sigma = out + NB*KK;    // (B,N,K)

    prep_kernel<<<NB/4, 128>>>(mu_q, sigma_q, sigma_p, phi, gen, out_sigma);
    pairA_kernel<<<dim3(JSPLIT, NB/RPB), 256>>>(beta);
    finish_kernel<<<NB/16, 256>>>(mu_q, mu_p, sigma_p, out_mu);
}